// round 5
// baseline (speedup 1.0000x reference)
#include <cuda_runtime.h>
#include <math.h>
#include <stdint.h>

// ---------------------------------------------------------------------------
// Problem constants (fixed by the dataset)
// ---------------------------------------------------------------------------
namespace {
constexpr int NN   = 100000;   // nodes per type
constexpr int EE   = 500000;   // edges per relation
constexpr int CIN  = 128;
constexpr int COUT = 128;
constexpr int NH   = 8;
constexpr int DKH  = 16;
constexpr int DFF  = 512;
constexpr int NSCAN   = 3 * NN;
constexpr int SCAN_BS = 1024;
constexpr int SCAN_NB = (NSCAN + SCAN_BS - 1) / SCAN_BS;  // 293

constexpr int AS_STRIDE = 36;    // [128][36]  bank = 4m+k  (conflict-free frags)
constexpr int BS_STRIDE = 136;   // [32][136]  bank = 8k+n  (conflict-free frags)
constexpr int TG_SMEM = (2 * 128 * AS_STRIDE + 2 * 32 * BS_STRIDE) * 4;  // 71680 B
}

// ---------------------------------------------------------------------------
// Device scratch (static globals: allocation-free rule)
// ---------------------------------------------------------------------------
__device__ float g_qa[(size_t)NN * COUT];
__device__ float g_qb[(size_t)NN * COUT];
__device__ float g_kv[3][(size_t)NN * 2 * COUT];   // per relation: [N][kp(128)|vp(128)]
__device__ float g_t[2][(size_t)NN * COUT];        // aggregated messages (a, b)
__device__ float g_x[2][(size_t)NN * COUT];        // post-LN activations
__device__ float g_ff[(size_t)NN * DFF];           // FFN hidden (reused per type)
__device__ float g_Wkv[3][CIN * 2 * COUT];         // fused (Wk@att*pri/4 | Wv@msg)
__device__ float g_bkv[3][2 * COUT];
__device__ int   g_deg[NSCAN];
__device__ int   g_off[NSCAN];
__device__ int   g_wpos[NSCAN];
__device__ int   g_csr[3 * EE];
__device__ int   g_part[512];
__device__ int   g_part_scan[512];
__device__ int   g_i32;                            // 1 => edge indices are int32

// ---------------------------------------------------------------------------
// Fused per-relation weight prep
// ---------------------------------------------------------------------------
__global__ void prep_weights(const float* __restrict__ Wk, const float* __restrict__ bk,
                             const float* __restrict__ Wv, const float* __restrict__ bv,
                             const float* __restrict__ pri, const float* __restrict__ att,
                             const float* __restrict__ msg) {
    int idx = blockIdx.x * blockDim.x + threadIdx.x;
    if (idx >= 6 * CIN * COUT) return;
    int combo = idx >> 14;
    int rem   = idx & 16383;
    int i = rem >> 7;
    int j = rem & 127;
    int r = combo >> 1;
    int kind = combo & 1;
    int t = (r == 1) ? 1 : 0;
    const float* Ws = (kind ? Wv : Wk) + (size_t)t * CIN * COUT;
    const float* bs = (kind ? bv : bk) + t * COUT;
    const float* Rm = (kind ? msg : att) + (size_t)r * NH * DKH * DKH;
    int h = j >> 4, jj = j & 15;
    float scale = kind ? 1.0f : pri[r * NH + h] * 0.25f;
    float s = 0.f;
#pragma unroll
    for (int d = 0; d < DKH; d++)
        s += Ws[(size_t)i * COUT + h * DKH + d] * Rm[h * DKH * DKH + d * DKH + jj];
    g_Wkv[r][i * 256 + kind * 128 + j] = s * scale;
    if (i == 0) {
        float b = 0.f;
#pragma unroll
        for (int d = 0; d < DKH; d++)
            b += bs[h * DKH + d] * Rm[h * DKH * DKH + d * DKH + jj];
        g_bkv[r][kind * 128 + j] = b * scale;
    }
}

// ---------------------------------------------------------------------------
// 3xTF32 tensor-core GEMM, hi/lo split precomputed into shared memory.
// Inner loop is pure LDS + mma.sync.m16n8k8.tf32 (no conversions).
// ---------------------------------------------------------------------------
__device__ __forceinline__ void tf32_split(float v, uint32_t& hi, uint32_t& lo) {
    uint32_t h;
    asm("cvt.rna.tf32.f32 %0, %1;" : "=r"(h) : "f"(v));
    float lf = v - __uint_as_float(h);     // exact residual
    uint32_t l;
    asm("cvt.rna.tf32.f32 %0, %1;" : "=r"(l) : "f"(lf));
    hi = h; lo = l;
}

__device__ __forceinline__ void mma8(float* c, const uint32_t* a, const uint32_t* b) {
    asm volatile(
        "mma.sync.aligned.m16n8k8.row.col.f32.tf32.tf32.f32 "
        "{%0,%1,%2,%3}, {%4,%5,%6,%7}, {%8,%9}, {%0,%1,%2,%3};"
        : "+f"(c[0]), "+f"(c[1]), "+f"(c[2]), "+f"(c[3])
        : "r"(a[0]), "r"(a[1]), "r"(a[2]), "r"(a[3]), "r"(b[0]), "r"(b[1]));
}

__device__ __forceinline__ void store_split4(uint32_t* hi, uint32_t* lo, float4 v) {
    uint4 h, l;
    tf32_split(v.x, h.x, l.x);
    tf32_split(v.y, h.y, l.y);
    tf32_split(v.z, h.z, l.z);
    tf32_split(v.w, h.w, l.w);
    *reinterpret_cast<uint4*>(hi) = h;
    *reinterpret_cast<uint4*>(lo) = l;
}

template<bool RELU_A, bool RELU_OUT, bool RES>
__global__ __launch_bounds__(256, 2) void tgemm(
        const float* __restrict__ A, const float* __restrict__ B,
        const float* __restrict__ bias, const float* __restrict__ Rp,
        float* __restrict__ C, int M, int Ncols, int K) {
    extern __shared__ uint32_t sm[];
    uint32_t* As_hi = sm;                                  // [128][36]
    uint32_t* As_lo = sm + 128 * AS_STRIDE;
    uint32_t* Bs_hi = sm + 2 * 128 * AS_STRIDE;            // [32][136]
    uint32_t* Bs_lo = Bs_hi + 32 * BS_STRIDE;

    int tid = threadIdx.x;
    int wid = tid >> 5, lane = tid & 31;
    int wm = wid & 3, wn = wid >> 2;       // 4x2 warp grid
    int wrow = wm * 32, wcol = wn * 64;
    int row0 = blockIdx.y * 128;
    int col0 = blockIdx.x * 128;

    float acc[2][8][4];
#pragma unroll
    for (int mt = 0; mt < 2; mt++)
#pragma unroll
        for (int nt = 0; nt < 8; nt++)
#pragma unroll
            for (int r = 0; r < 4; r++) acc[mt][nt][r] = 0.f;

    const int arow = tid >> 1;
    const int acol = (tid & 1) * 16;
    const int brow = tid >> 3;
    const int bcol = (tid & 7) * 16;
    const int agr  = row0 + arow;

    float4 a_st[4], b_st[4];
    if (agr < M) {
#pragma unroll
        for (int i = 0; i < 4; i++) {
            float4 v = *reinterpret_cast<const float4*>(A + (size_t)agr * K + acol + 4 * i);
            if (RELU_A) {
                v.x = fmaxf(v.x, 0.f); v.y = fmaxf(v.y, 0.f);
                v.z = fmaxf(v.z, 0.f); v.w = fmaxf(v.w, 0.f);
            }
            a_st[i] = v;
        }
    } else {
#pragma unroll
        for (int i = 0; i < 4; i++) a_st[i] = make_float4(0.f, 0.f, 0.f, 0.f);
    }
#pragma unroll
    for (int i = 0; i < 4; i++)
        b_st[i] = *reinterpret_cast<const float4*>(B + (size_t)brow * Ncols + col0 + bcol + 4 * i);

    for (int kk = 0; kk < K; kk += 32) {
#pragma unroll
        for (int i = 0; i < 4; i++) {
            int ai = arow * AS_STRIDE + acol + 4 * i;
            int bi = brow * BS_STRIDE + bcol + 4 * i;
            store_split4(&As_hi[ai], &As_lo[ai], a_st[i]);
            store_split4(&Bs_hi[bi], &Bs_lo[bi], b_st[i]);
        }
        __syncthreads();

        // prefetch next K-tile (overlaps the MMA phase below)
        if (kk + 32 < K) {
            if (agr < M) {
#pragma unroll
                for (int i = 0; i < 4; i++) {
                    float4 v = *reinterpret_cast<const float4*>(A + (size_t)agr * K + kk + 32 + acol + 4 * i);
                    if (RELU_A) {
                        v.x = fmaxf(v.x, 0.f); v.y = fmaxf(v.y, 0.f);
                        v.z = fmaxf(v.z, 0.f); v.w = fmaxf(v.w, 0.f);
                    }
                    a_st[i] = v;
                }
            }
#pragma unroll
            for (int i = 0; i < 4; i++)
                b_st[i] = *reinterpret_cast<const float4*>(B + (size_t)(kk + 32 + brow) * Ncols + col0 + bcol + 4 * i);
        }

#pragma unroll
        for (int ks = 0; ks < 4; ks++) {
            int k0 = ks * 8;
            uint32_t ahi[2][4], alo[2][4];
#pragma unroll
            for (int mt = 0; mt < 2; mt++) {
#pragma unroll
                for (int r = 0; r < 4; r++) {
                    int mr = (lane >> 2) + (r & 1) * 8;
                    int kr = (lane & 3) + (r >> 1) * 4;
                    int idx = (wrow + mt * 16 + mr) * AS_STRIDE + k0 + kr;
                    ahi[mt][r] = As_hi[idx];
                    alo[mt][r] = As_lo[idx];
                }
            }
#pragma unroll
            for (int nt = 0; nt < 8; nt++) {
                uint32_t bhi[2], blo[2];
#pragma unroll
                for (int r = 0; r < 2; r++) {
                    int kr = (lane & 3) + r * 4;
                    int nr = lane >> 2;
                    int idx = (k0 + kr) * BS_STRIDE + wcol + nt * 8 + nr;
                    bhi[r] = Bs_hi[idx];
                    blo[r] = Bs_lo[idx];
                }
#pragma unroll
                for (int mt = 0; mt < 2; mt++) {
                    mma8(acc[mt][nt], ahi[mt], bhi);
                    mma8(acc[mt][nt], alo[mt], bhi);
                    mma8(acc[mt][nt], ahi[mt], blo);
                }
            }
        }
        __syncthreads();
    }

    // epilogue
#pragma unroll
    for (int mt = 0; mt < 2; mt++) {
#pragma unroll
        for (int nt = 0; nt < 8; nt++) {
            int gr = row0 + wrow + mt * 16 + (lane >> 2);
            int gc = col0 + wcol + nt * 8 + (lane & 3) * 2;
            float2 bb = *reinterpret_cast<const float2*>(&bias[gc]);
#pragma unroll
            for (int hh = 0; hh < 2; hh++) {
                int r = gr + hh * 8;
                if (r >= M) continue;
                float o0 = acc[mt][nt][hh * 2 + 0] + bb.x;
                float o1 = acc[mt][nt][hh * 2 + 1] + bb.y;
                if (RES) {
                    float2 rr = *reinterpret_cast<const float2*>(Rp + (size_t)r * Ncols + gc);
                    o0 += rr.x; o1 += rr.y;
                }
                if (RELU_OUT) { o0 = fmaxf(o0, 0.f); o1 = fmaxf(o1, 0.f); }
                *reinterpret_cast<float2*>(C + (size_t)r * Ncols + gc) = make_float2(o0, o1);
            }
        }
    }
}

// ---------------------------------------------------------------------------
// Edge-index helpers: dtype (int32 vs int64) detected at runtime
// ---------------------------------------------------------------------------
__global__ void zero_deg() {
    int i = blockIdx.x * blockDim.x + threadIdx.x;
    if (i == 0) g_i32 = 0;
    if (i < NSCAN) g_deg[i] = 0;
}

__global__ void detect_i32(const int* __restrict__ d) {
    int i = blockIdx.x * blockDim.x + threadIdx.x;
    if (i >= EE / 2) return;
    if (d[2 * i + 1] != 0) g_i32 = 1;
}

__device__ __forceinline__ int eidx(const void* p, int i, int is32) {
    return is32 ? ((const int*)p)[i] : (int)((const long long*)p)[i];
}

__global__ void count_deg(const void* __restrict__ dst, int r) {
    int i = blockIdx.x * blockDim.x + threadIdx.x;
    if (i >= EE) return;
    int is32 = g_i32;
    atomicAdd(&g_deg[r * NN + eidx(dst, i, is32)], 1);
}

__global__ void scatter_edges(const void* __restrict__ src, const void* __restrict__ dst, int r) {
    int i = blockIdx.x * blockDim.x + threadIdx.x;
    if (i >= EE) return;
    int is32 = g_i32;
    int d = eidx(dst, i, is32);
    int p = atomicAdd(&g_wpos[r * NN + d], 1);
    g_csr[p] = eidx(src, i, is32);
}

// ---------------------------------------------------------------------------
// Exclusive scan over g_deg[3N]
// ---------------------------------------------------------------------------
__global__ void scan1() {
    __shared__ int sh[SCAN_BS];
    int i = blockIdx.x * SCAN_BS + threadIdx.x;
    sh[threadIdx.x] = (i < NSCAN) ? g_deg[i] : 0;
    __syncthreads();
    for (int ofs = SCAN_BS / 2; ofs > 0; ofs >>= 1) {
        if (threadIdx.x < ofs) sh[threadIdx.x] += sh[threadIdx.x + ofs];
        __syncthreads();
    }
    if (threadIdx.x == 0) g_part[blockIdx.x] = sh[0];
}

__global__ void scan2() {
    __shared__ int a[512], b[512];
    int t = threadIdx.x;
    int v = (t < SCAN_NB) ? g_part[t] : 0;
    a[t] = v; __syncthreads();
    int* s = a; int* d = b;
    for (int ofs = 1; ofs < 512; ofs <<= 1) {
        int x = s[t];
        if (t >= ofs) x += s[t - ofs];
        d[t] = x; __syncthreads();
        int* tmp = s; s = d; d = tmp;
    }
    g_part_scan[t] = s[t] - v;
}

__global__ void scan3() {
    __shared__ int a[SCAN_BS], b[SCAN_BS];
    int t = threadIdx.x;
    int i = blockIdx.x * SCAN_BS + t;
    int v = (i < NSCAN) ? g_deg[i] : 0;
    a[t] = v; __syncthreads();
    int* s = a; int* d = b;
    for (int ofs = 1; ofs < SCAN_BS; ofs <<= 1) {
        int x = s[t];
        if (t >= ofs) x += s[t - ofs];
        d[t] = x; __syncthreads();
        int* tmp = s; s = d; d = tmp;
    }
    if (i < NSCAN) {
        int excl = s[t] - v + g_part_scan[blockIdx.x];
        g_off[i]  = excl;
        g_wpos[i] = excl;
    }
}

// ---------------------------------------------------------------------------
// Dst-centric attention aggregation: one warp per destination node.
// ---------------------------------------------------------------------------
__device__ __forceinline__ void rel_accum(int node, int lane, int r,
                                          const float* __restrict__ kvbuf,
                                          float4 q, float4& res) {
    int off = g_off[r * NN + node];
    int dg  = g_deg[r * NN + node];
    float4 acc = make_float4(0.f, 0.f, 0.f, 0.f);
    float z = 0.f;
    int e = 0;
    for (; e + 2 <= dg; e += 2) {
        int s0 = g_csr[off + e];
        int s1 = g_csr[off + e + 1];
        const float4* kv0 = reinterpret_cast<const float4*>(kvbuf + (size_t)s0 * 256);
        const float4* kv1 = reinterpret_cast<const float4*>(kvbuf + (size_t)s1 * 256);
        float4 kp0 = kv0[lane];
        float4 kp1 = kv1[lane];
        float4 vp0 = kv0[32 + lane];
        float4 vp1 = kv1[32 + lane];
        float p0 = q.x * kp0.x + q.y * kp0.y + q.z * kp0.z + q.w * kp0.w;
        float p1 = q.x * kp1.x + q.y * kp1.y + q.z * kp1.z + q.w * kp1.w;
        p0 += __shfl_xor_sync(0xffffffffu, p0, 1);
        p1 += __shfl_xor_sync(0xffffffffu, p1, 1);
        p0 += __shfl_xor_sync(0xffffffffu, p0, 2);
        p1 += __shfl_xor_sync(0xffffffffu, p1, 2);
        float e0 = expf(p0), e1 = expf(p1);
        z += e0 + e1;
        acc.x += e0 * vp0.x + e1 * vp1.x;
        acc.y += e0 * vp0.y + e1 * vp1.y;
        acc.z += e0 * vp0.z + e1 * vp1.z;
        acc.w += e0 * vp0.w + e1 * vp1.w;
    }
    if (e < dg) {
        int s = g_csr[off + e];
        const float4* kv = reinterpret_cast<const float4*>(kvbuf + (size_t)s * 256);
        float4 kp = kv[lane];
        float4 vp = kv[32 + lane];
        float p = q.x * kp.x + q.y * kp.y + q.z * kp.z + q.w * kp.w;
        p += __shfl_xor_sync(0xffffffffu, p, 1);
        p += __shfl_xor_sync(0xffffffffu, p, 2);
        float eh = expf(p);
        z += eh;
        acc.x += eh * vp.x; acc.y += eh * vp.y;
        acc.z += eh * vp.z; acc.w += eh * vp.w;
    }
    if (z > 0.f) {
        float inv = 1.f / z;
        res.x += acc.x * inv; res.y += acc.y * inv;
        res.z += acc.z * inv; res.w += acc.w * inv;
    }
}

__global__ void agg_type_b() {   // relation 0: a -> b
    int w = (blockIdx.x * blockDim.x + threadIdx.x) >> 5;
    if (w >= NN) return;
    int lane = threadIdx.x & 31;
    float4 q = *reinterpret_cast<const float4*>(g_qb + (size_t)w * 128 + lane * 4);
    float4 res = make_float4(0.f, 0.f, 0.f, 0.f);
    rel_accum(w, lane, 0, g_kv[0], q, res);
    *reinterpret_cast<float4*>(g_t[1] + (size_t)w * 128 + lane * 4) = res;
}

__global__ void agg_type_a() {   // relations 1 (b->a) + 2 (a->a), summed
    int w = (blockIdx.x * blockDim.x + threadIdx.x) >> 5;
    if (w >= NN) return;
    int lane = threadIdx.x & 31;
    float4 q = *reinterpret_cast<const float4*>(g_qa + (size_t)w * 128 + lane * 4);
    float4 res = make_float4(0.f, 0.f, 0.f, 0.f);
    rel_accum(w, lane, 1, g_kv[1], q, res);
    rel_accum(w, lane, 2, g_kv[2], q, res);
    *reinterpret_cast<float4*>(g_t[0] + (size_t)w * 128 + lane * 4) = res;
}

// ---------------------------------------------------------------------------
// Row LayerNorm (warp per row, 128 cols)
// ---------------------------------------------------------------------------
__global__ void layernorm(float* __restrict__ X, const float* __restrict__ gamma,
                          const float* __restrict__ beta) {
    int w = (blockIdx.x * blockDim.x + threadIdx.x) >> 5;
    if (w >= NN) return;
    int lane = threadIdx.x & 31;
    float4 v = *reinterpret_cast<const float4*>(X + (size_t)w * 128 + lane * 4);
    float s  = v.x + v.y + v.z + v.w;
    float s2 = v.x * v.x + v.y * v.y + v.z * v.z + v.w * v.w;
#pragma unroll
    for (int ofs = 16; ofs > 0; ofs >>= 1) {
        s  += __shfl_xor_sync(0xffffffffu, s, ofs);
        s2 += __shfl_xor_sync(0xffffffffu, s2, ofs);
    }
    float mu   = s * (1.f / 128.f);
    float var  = s2 * (1.f / 128.f) - mu * mu;
    float rstd = rsqrtf(var + 1e-5f);
    float4 g = *reinterpret_cast<const float4*>(gamma + lane * 4);
    float4 b = *reinterpret_cast<const float4*>(beta + lane * 4);
    float4 o;
    o.x = (v.x - mu) * rstd * g.x + b.x;
    o.y = (v.y - mu) * rstd * g.y + b.y;
    o.z = (v.z - mu) * rstd * g.z + b.z;
    o.w = (v.w - mu) * rstd * g.w + b.w;
    *reinterpret_cast<float4*>(X + (size_t)w * 128 + lane * 4) = o;
}

// ---------------------------------------------------------------------------
// Launch
// ---------------------------------------------------------------------------
extern "C" void kernel_launch(void* const* d_in, const int* in_sizes, int n_in,
                              void* d_out, int out_size) {
    const float* h_a   = (const float*)d_in[0];
    const float* h_b   = (const float*)d_in[1];
    const float* Wk    = (const float*)d_in[2];
    const float* bk    = (const float*)d_in[3];
    const float* Wq    = (const float*)d_in[4];
    const float* bq    = (const float*)d_in[5];
    const float* Wv    = (const float*)d_in[6];
    const float* bv    = (const float*)d_in[7];
    const float* Wa    = (const float*)d_in[8];
    const float* ba    = (const float*)d_in[9];
    const float* gamma = (const float*)d_in[10];
    const float* beta  = (const float*)d_in[11];
    const float* W1    = (const float*)d_in[12];
    const float* b1    = (const float*)d_in[13];
    const float* W2    = (const float*)d_in[14];
    const float* b2    = (const float*)d_in[15];
    const float* pri   = (const float*)d_in[16];
    const float* att   = (const float*)d_in[17];
    const float* msg   = (const float*)d_in[18];
    const void* src0 = d_in[19]; const void* dst0 = d_in[20];
    const void* src1 = d_in[21]; const void* dst1 = d_in[22];
    const void* src2 = d_in[23]; const void* dst2 = d_in[24];
    float* out = (float*)d_out;

    float *p_qa, *p_qb, *p_kv, *p_t, *p_x, *p_ff, *p_Wkv, *p_bkv;
    cudaGetSymbolAddress((void**)&p_qa,  g_qa);
    cudaGetSymbolAddress((void**)&p_qb,  g_qb);
    cudaGetSymbolAddress((void**)&p_kv,  g_kv);
    cudaGetSymbolAddress((void**)&p_t,   g_t);
    cudaGetSymbolAddress((void**)&p_x,   g_x);
    cudaGetSymbolAddress((void**)&p_ff,  g_ff);
    cudaGetSymbolAddress((void**)&p_Wkv, g_Wkv);
    cudaGetSymbolAddress((void**)&p_bkv, g_bkv);

    // opt-in to 70KB dynamic smem (host-side attribute set; capture-safe)
    cudaFuncSetAttribute(tgemm<false,false,false>, cudaFuncAttributeMaxDynamicSharedMemorySize, TG_SMEM);
    cudaFuncSetAttribute(tgemm<true,false,true>,   cudaFuncAttributeMaxDynamicSharedMemorySize, TG_SMEM);
    cudaFuncSetAttribute(tgemm<false,true,false>,  cudaFuncAttributeMaxDynamicSharedMemorySize, TG_SMEM);

    const int gy = (NN + 127) / 128;           // 782
    const int eb = (EE + 255) / 256;
    const int wb = (NN * 32) / 256;            // 12500 (exact)

    // 0. reset + edge dtype detection
    zero_deg<<<(NSCAN + 255) / 256, 256>>>();
    detect_i32<<<(EE / 2 + 255) / 256, 256>>>((const int*)dst0);

    // 1. fused relation weights
    prep_weights<<<(6 * CIN * COUT + 255) / 256, 256>>>(Wk, bk, Wv, bv, pri, att, msg);

    // 2. projections (q per type; fused kp|vp per relation)
    tgemm<false,false,false><<<dim3(1, gy), 256, TG_SMEM>>>(h_a, Wq,                 bq,       nullptr, p_qa, NN, 128, 128);
    tgemm<false,false,false><<<dim3(1, gy), 256, TG_SMEM>>>(h_b, Wq + 128 * 128,     bq + 128, nullptr, p_qb, NN, 128, 128);
    tgemm<false,false,false><<<dim3(2, gy), 256, TG_SMEM>>>(h_a, p_Wkv,              p_bkv,       nullptr, p_kv,                      NN, 256, 128);
    tgemm<false,false,false><<<dim3(2, gy), 256, TG_SMEM>>>(h_b, p_Wkv + 128 * 256,  p_bkv + 256, nullptr, p_kv + (size_t)NN * 256,   NN, 256, 128);
    tgemm<false,false,false><<<dim3(2, gy), 256, TG_SMEM>>>(h_a, p_Wkv + 2*128*256,  p_bkv + 512, nullptr, p_kv + 2*(size_t)NN * 256, NN, 256, 128);

    // 3. CSR build (degree -> scan -> scatter)
    count_deg<<<eb, 256>>>(dst0, 0);
    count_deg<<<eb, 256>>>(dst1, 1);
    count_deg<<<eb, 256>>>(dst2, 2);
    scan1<<<SCAN_NB, SCAN_BS>>>();
    scan2<<<1, 512>>>();
    scan3<<<SCAN_NB, SCAN_BS>>>();
    scatter_edges<<<eb, 256>>>(src0, dst0, 0);
    scatter_edges<<<eb, 256>>>(src1, dst1, 1);
    scatter_edges<<<eb, 256>>>(src2, dst2, 2);

    // 4. attention aggregation (warp per dst node, no atomics)
    agg_type_b<<<wb, 256>>>();
    agg_type_a<<<wb, 256>>>();

    // 5. per-type update: relu(t)@Wa + ba + h -> LN -> relu(@W1+b1)@W2 + b2
    for (int t = 0; t < 2; t++) {
        const float* hres = t ? h_b : h_a;
        tgemm<true,false,true><<<dim3(1, gy), 256, TG_SMEM>>>(p_t + (size_t)t * NN * 128, Wa + (size_t)t * 128 * 128,
                                                              ba + t * 128, hres,
                                                              p_x + (size_t)t * NN * 128, NN, 128, 128);
        layernorm<<<wb, 256>>>(p_x + (size_t)t * NN * 128, gamma + t * 128, beta + t * 128);
        tgemm<false,true,false><<<dim3(4, gy), 256, TG_SMEM>>>(p_x + (size_t)t * NN * 128, W1 + (size_t)t * 128 * 512,
                                                               b1 + t * 512, nullptr, p_ff, NN, 512, 128);
        tgemm<false,false,false><<<dim3(1, gy), 256, TG_SMEM>>>(p_ff, W2 + (size_t)t * 512 * 128,
                                                                b2 + t * 128, nullptr,
                                                                out + (size_t)t * NN * 128, NN, 128, 512);
    }
}

// round 6
// speedup vs baseline: 1.7069x; 1.7069x over previous
#include <cuda_runtime.h>
#include <cuda_bf16.h>
#include <math.h>
#include <stdint.h>

// ---------------------------------------------------------------------------
// Problem constants (fixed by the dataset)
// ---------------------------------------------------------------------------
namespace {
constexpr int NN   = 100000;   // nodes per type
constexpr int EE   = 500000;   // edges per relation
constexpr int CIN  = 128;
constexpr int COUT = 128;
constexpr int NH   = 8;
constexpr int DKH  = 16;
constexpr int DFF  = 512;
constexpr int NSCAN   = 3 * NN;
constexpr int SCAN_BS = 1024;
constexpr int SCAN_NB = (NSCAN + SCAN_BS - 1) / SCAN_BS;  // 293

constexpr int AROW = 40;    // A smem row stride in bf16 (80B = 5x16B -> ldmatrix conflict-free)
constexpr int BROW = 136;   // B smem row stride in bf16 (272B = 17x16B -> conflict-free)
}

// ---------------------------------------------------------------------------
// Device scratch (static globals: allocation-free rule)
// ---------------------------------------------------------------------------
__device__ float g_qa[(size_t)NN * COUT];
__device__ float g_qb[(size_t)NN * COUT];
__device__ float g_kv[3][(size_t)NN * 2 * COUT];   // per relation: [N][kp(128)|vp(128)]
__device__ float g_t[2][(size_t)NN * COUT];        // aggregated messages (a, b)
__device__ float g_x[2][(size_t)NN * COUT];        // post-LN activations
__device__ float g_ff[(size_t)NN * DFF];           // FFN hidden (reused per type)
__device__ float g_Wkv[3][CIN * 2 * COUT];         // fused (Wk@att*pri/4 | Wv@msg)
__device__ float g_bkv[3][2 * COUT];
__device__ int   g_deg[NSCAN];
__device__ int   g_off[NSCAN];
__device__ int   g_wpos[NSCAN];
__device__ int   g_csr[3 * EE];
__device__ int   g_part[512];
__device__ int   g_part_scan[512];
__device__ int   g_i32;                            // 1 => edge indices are int32

// ---------------------------------------------------------------------------
// Fused per-relation weight prep
// ---------------------------------------------------------------------------
__global__ void prep_weights(const float* __restrict__ Wk, const float* __restrict__ bk,
                             const float* __restrict__ Wv, const float* __restrict__ bv,
                             const float* __restrict__ pri, const float* __restrict__ att,
                             const float* __restrict__ msg) {
    int idx = blockIdx.x * blockDim.x + threadIdx.x;
    if (idx >= 6 * CIN * COUT) return;
    int combo = idx >> 14;
    int rem   = idx & 16383;
    int i = rem >> 7;
    int j = rem & 127;
    int r = combo >> 1;
    int kind = combo & 1;
    int t = (r == 1) ? 1 : 0;
    const float* Ws = (kind ? Wv : Wk) + (size_t)t * CIN * COUT;
    const float* bs = (kind ? bv : bk) + t * COUT;
    const float* Rm = (kind ? msg : att) + (size_t)r * NH * DKH * DKH;
    int h = j >> 4, jj = j & 15;
    float scale = kind ? 1.0f : pri[r * NH + h] * 0.25f;
    float s = 0.f;
#pragma unroll
    for (int d = 0; d < DKH; d++)
        s += Ws[(size_t)i * COUT + h * DKH + d] * Rm[h * DKH * DKH + d * DKH + jj];
    g_Wkv[r][i * 256 + kind * 128 + j] = s * scale;
    if (i == 0) {
        float b = 0.f;
#pragma unroll
        for (int d = 0; d < DKH; d++)
            b += bs[h * DKH + d] * Rm[h * DKH * DKH + d * DKH + jj];
        g_bkv[r][kind * 128 + j] = b * scale;
    }
}

// ---------------------------------------------------------------------------
// bf16 double-pseudo GEMM (3-term: HiHi + LoHi + HiLo) on mma.m16n8k16,
// fragments via ldmatrix.x4 — inner loop is ldmatrix + MMA only.
// ---------------------------------------------------------------------------
__device__ __forceinline__ void mma16(float* c, const uint32_t* a, const uint32_t* b) {
    asm volatile(
        "mma.sync.aligned.m16n8k16.row.col.f32.bf16.bf16.f32 "
        "{%0,%1,%2,%3}, {%4,%5,%6,%7}, {%8,%9}, {%0,%1,%2,%3};"
        : "+f"(c[0]), "+f"(c[1]), "+f"(c[2]), "+f"(c[3])
        : "r"(a[0]), "r"(a[1]), "r"(a[2]), "r"(a[3]), "r"(b[0]), "r"(b[1]));
}

__device__ __forceinline__ void ldmx4(uint32_t* r, uint32_t saddr) {
    asm volatile("ldmatrix.sync.aligned.m8n8.x4.shared.b16 {%0,%1,%2,%3}, [%4];"
                 : "=r"(r[0]), "=r"(r[1]), "=r"(r[2]), "=r"(r[3]) : "r"(saddr));
}
__device__ __forceinline__ void ldmx4t(uint32_t* r, uint32_t saddr) {
    asm volatile("ldmatrix.sync.aligned.m8n8.x4.trans.shared.b16 {%0,%1,%2,%3}, [%4];"
                 : "=r"(r[0]), "=r"(r[1]), "=r"(r[2]), "=r"(r[3]) : "r"(saddr));
}

// split fp32 -> bf16 hi + bf16 residual, store 4 k-adjacent values packed
__device__ __forceinline__ void cvt_store4(__nv_bfloat16* hi, __nv_bfloat16* lo, float4 v) {
    __nv_bfloat162 h0 = __floats2bfloat162_rn(v.x, v.y);
    __nv_bfloat162 h1 = __floats2bfloat162_rn(v.z, v.w);
    __nv_bfloat162 l0 = __floats2bfloat162_rn(v.x - __bfloat162float(h0.x),
                                              v.y - __bfloat162float(h0.y));
    __nv_bfloat162 l1 = __floats2bfloat162_rn(v.z - __bfloat162float(h1.x),
                                              v.w - __bfloat162float(h1.y));
    *reinterpret_cast<__nv_bfloat162*>(hi)     = h0;
    *reinterpret_cast<__nv_bfloat162*>(hi + 2) = h1;
    *reinterpret_cast<__nv_bfloat162*>(lo)     = l0;
    *reinterpret_cast<__nv_bfloat162*>(lo + 2) = l1;
}

template<bool RELU_A, bool RELU_OUT, bool RES>
__global__ __launch_bounds__(256, 2) void tgemm(
        const float* __restrict__ A, const float* __restrict__ B,
        const float* __restrict__ bias, const float* __restrict__ Rp,
        float* __restrict__ C, int M, int Ncols, int K) {
    __shared__ __align__(16) __nv_bfloat16 As_hi[128 * AROW];
    __shared__ __align__(16) __nv_bfloat16 As_lo[128 * AROW];
    __shared__ __align__(16) __nv_bfloat16 Bs_hi[32 * BROW];
    __shared__ __align__(16) __nv_bfloat16 Bs_lo[32 * BROW];

    int tid = threadIdx.x;
    int wid = tid >> 5, lane = tid & 31;
    int wm = wid & 3, wn = wid >> 2;       // 4x2 warp grid, warp tile 32x64
    int wrow = wm * 32, wcol = wn * 64;
    int row0 = blockIdx.y * 128;
    int col0 = blockIdx.x * 128;

    float acc[2][8][4];
#pragma unroll
    for (int mt = 0; mt < 2; mt++)
#pragma unroll
        for (int nt = 0; nt < 8; nt++)
#pragma unroll
            for (int r = 0; r < 4; r++) acc[mt][nt][r] = 0.f;

    // staging: A thread -> (row tid>>1, 16 cols), B -> (row tid>>3, 16 cols)
    const int arow = tid >> 1;
    const int acol = (tid & 1) * 16;
    const int brow = tid >> 3;
    const int bcol = (tid & 7) * 16;
    const int agr  = row0 + arow;

    // per-thread ldmatrix base offsets (8-row groups per matrix id)
    const int lrow = (lane & 7) + ((lane >> 3) & 1) * 8;   // row within 16
    const int lcol = (lane >> 4) * 8;                      // col 8-offset
    const uint32_t sa_hi = (uint32_t)__cvta_generic_to_shared(As_hi);
    const uint32_t sa_lo = (uint32_t)__cvta_generic_to_shared(As_lo);
    const uint32_t sb_hi = (uint32_t)__cvta_generic_to_shared(Bs_hi);
    const uint32_t sb_lo = (uint32_t)__cvta_generic_to_shared(Bs_lo);

    float4 a_st[4], b_st[4];
    if (agr < M) {
#pragma unroll
        for (int i = 0; i < 4; i++) {
            float4 v = *reinterpret_cast<const float4*>(A + (size_t)agr * K + acol + 4 * i);
            if (RELU_A) {
                v.x = fmaxf(v.x, 0.f); v.y = fmaxf(v.y, 0.f);
                v.z = fmaxf(v.z, 0.f); v.w = fmaxf(v.w, 0.f);
            }
            a_st[i] = v;
        }
    } else {
#pragma unroll
        for (int i = 0; i < 4; i++) a_st[i] = make_float4(0.f, 0.f, 0.f, 0.f);
    }
#pragma unroll
    for (int i = 0; i < 4; i++)
        b_st[i] = *reinterpret_cast<const float4*>(B + (size_t)brow * Ncols + col0 + bcol + 4 * i);

    for (int kk = 0; kk < K; kk += 32) {
#pragma unroll
        for (int i = 0; i < 4; i++) {
            int ai = arow * AROW + acol + 4 * i;
            int bi = brow * BROW + bcol + 4 * i;
            cvt_store4(&As_hi[ai], &As_lo[ai], a_st[i]);
            cvt_store4(&Bs_hi[bi], &Bs_lo[bi], b_st[i]);
        }
        __syncthreads();

        // prefetch next K-tile (overlaps MMA phase)
        if (kk + 32 < K) {
            if (agr < M) {
#pragma unroll
                for (int i = 0; i < 4; i++) {
                    float4 v = *reinterpret_cast<const float4*>(A + (size_t)agr * K + kk + 32 + acol + 4 * i);
                    if (RELU_A) {
                        v.x = fmaxf(v.x, 0.f); v.y = fmaxf(v.y, 0.f);
                        v.z = fmaxf(v.z, 0.f); v.w = fmaxf(v.w, 0.f);
                    }
                    a_st[i] = v;
                }
            }
#pragma unroll
            for (int i = 0; i < 4; i++)
                b_st[i] = *reinterpret_cast<const float4*>(B + (size_t)(kk + 32 + brow) * Ncols + col0 + bcol + 4 * i);
        }

#pragma unroll
        for (int kc = 0; kc < 2; kc++) {           // two k16 chunks per tile
            const int k0 = kc * 16;
            uint32_t ahi[2][4], alo[2][4];
#pragma unroll
            for (int mt = 0; mt < 2; mt++) {
                uint32_t off = (uint32_t)((wrow + mt * 16 + lrow) * AROW + k0 + lcol) * 2;
                ldmx4(ahi[mt], sa_hi + off);
                ldmx4(alo[mt], sa_lo + off);
            }
#pragma unroll
            for (int ng = 0; ng < 4; ng++) {       // n16 groups (2 nt each)
                uint32_t bhi[4], blo[4];
                uint32_t off = (uint32_t)((k0 + lrow) * BROW + wcol + ng * 16 + lcol) * 2;
                ldmx4t(bhi, sb_hi + off);
                ldmx4t(blo, sb_lo + off);
#pragma unroll
                for (int mt = 0; mt < 2; mt++) {
                    mma16(acc[mt][2 * ng],     ahi[mt], bhi);
                    mma16(acc[mt][2 * ng],     alo[mt], bhi);
                    mma16(acc[mt][2 * ng],     ahi[mt], blo);
                    mma16(acc[mt][2 * ng + 1], ahi[mt], bhi + 2);
                    mma16(acc[mt][2 * ng + 1], alo[mt], bhi + 2);
                    mma16(acc[mt][2 * ng + 1], ahi[mt], blo + 2);
                }
            }
        }
        __syncthreads();
    }

    // epilogue: c0/c1 at (row, col..col+1), c2/c3 at (row+8, ...)
#pragma unroll
    for (int mt = 0; mt < 2; mt++) {
#pragma unroll
        for (int nt = 0; nt < 8; nt++) {
            int gr = row0 + wrow + mt * 16 + (lane >> 2);
            int gc = col0 + wcol + nt * 8 + (lane & 3) * 2;
            float2 bb = *reinterpret_cast<const float2*>(&bias[gc]);
#pragma unroll
            for (int hh = 0; hh < 2; hh++) {
                int r = gr + hh * 8;
                if (r >= M) continue;
                float o0 = acc[mt][nt][hh * 2 + 0] + bb.x;
                float o1 = acc[mt][nt][hh * 2 + 1] + bb.y;
                if (RES) {
                    float2 rr = *reinterpret_cast<const float2*>(Rp + (size_t)r * Ncols + gc);
                    o0 += rr.x; o1 += rr.y;
                }
                if (RELU_OUT) { o0 = fmaxf(o0, 0.f); o1 = fmaxf(o1, 0.f); }
                *reinterpret_cast<float2*>(C + (size_t)r * Ncols + gc) = make_float2(o0, o1);
            }
        }
    }
}

// ---------------------------------------------------------------------------
// Edge-index helpers: dtype (int32 vs int64) detected at runtime
// ---------------------------------------------------------------------------
__global__ void zero_deg() {
    int i = blockIdx.x * blockDim.x + threadIdx.x;
    if (i == 0) g_i32 = 0;
    if (i < NSCAN) g_deg[i] = 0;
}

__global__ void detect_i32(const int* __restrict__ d) {
    int i = blockIdx.x * blockDim.x + threadIdx.x;
    if (i >= EE / 2) return;
    if (d[2 * i + 1] != 0) g_i32 = 1;
}

__device__ __forceinline__ int eidx(const void* p, int i, int is32) {
    return is32 ? ((const int*)p)[i] : (int)((const long long*)p)[i];
}

__global__ void count_deg(const void* __restrict__ dst, int r) {
    int i = blockIdx.x * blockDim.x + threadIdx.x;
    if (i >= EE) return;
    int is32 = g_i32;
    atomicAdd(&g_deg[r * NN + eidx(dst, i, is32)], 1);
}

__global__ void scatter_edges(const void* __restrict__ src, const void* __restrict__ dst, int r) {
    int i = blockIdx.x * blockDim.x + threadIdx.x;
    if (i >= EE) return;
    int is32 = g_i32;
    int d = eidx(dst, i, is32);
    int p = atomicAdd(&g_wpos[r * NN + d], 1);
    g_csr[p] = eidx(src, i, is32);
}

// ---------------------------------------------------------------------------
// Exclusive scan over g_deg[3N]
// ---------------------------------------------------------------------------
__global__ void scan1() {
    __shared__ int sh[SCAN_BS];
    int i = blockIdx.x * SCAN_BS + threadIdx.x;
    sh[threadIdx.x] = (i < NSCAN) ? g_deg[i] : 0;
    __syncthreads();
    for (int ofs = SCAN_BS / 2; ofs > 0; ofs >>= 1) {
        if (threadIdx.x < ofs) sh[threadIdx.x] += sh[threadIdx.x + ofs];
        __syncthreads();
    }
    if (threadIdx.x == 0) g_part[blockIdx.x] = sh[0];
}

__global__ void scan2() {
    __shared__ int a[512], b[512];
    int t = threadIdx.x;
    int v = (t < SCAN_NB) ? g_part[t] : 0;
    a[t] = v; __syncthreads();
    int* s = a; int* d = b;
    for (int ofs = 1; ofs < 512; ofs <<= 1) {
        int x = s[t];
        if (t >= ofs) x += s[t - ofs];
        d[t] = x; __syncthreads();
        int* tmp = s; s = d; d = tmp;
    }
    g_part_scan[t] = s[t] - v;
}

__global__ void scan3() {
    __shared__ int a[SCAN_BS], b[SCAN_BS];
    int t = threadIdx.x;
    int i = blockIdx.x * SCAN_BS + t;
    int v = (i < NSCAN) ? g_deg[i] : 0;
    a[t] = v; __syncthreads();
    int* s = a; int* d = b;
    for (int ofs = 1; ofs < SCAN_BS; ofs <<= 1) {
        int x = s[t];
        if (t >= ofs) x += s[t - ofs];
        d[t] = x; __syncthreads();
        int* tmp = s; s = d; d = tmp;
    }
    if (i < NSCAN) {
        int excl = s[t] - v + g_part_scan[blockIdx.x];
        g_off[i]  = excl;
        g_wpos[i] = excl;
    }
}

// ---------------------------------------------------------------------------
// Dst-centric attention aggregation: one warp per destination node.
// ---------------------------------------------------------------------------
__device__ __forceinline__ void rel_accum(int node, int lane, int r,
                                          const float* __restrict__ kvbuf,
                                          float4 q, float4& res) {
    int off = g_off[r * NN + node];
    int dg  = g_deg[r * NN + node];
    float4 acc = make_float4(0.f, 0.f, 0.f, 0.f);
    float z = 0.f;
    int e = 0;
    for (; e + 2 <= dg; e += 2) {
        int s0 = g_csr[off + e];
        int s1 = g_csr[off + e + 1];
        const float4* kv0 = reinterpret_cast<const float4*>(kvbuf + (size_t)s0 * 256);
        const float4* kv1 = reinterpret_cast<const float4*>(kvbuf + (size_t)s1 * 256);
        float4 kp0 = kv0[lane];
        float4 kp1 = kv1[lane];
        float4 vp0 = kv0[32 + lane];
        float4 vp1 = kv1[32 + lane];
        float p0 = q.x * kp0.x + q.y * kp0.y + q.z * kp0.z + q.w * kp0.w;
        float p1 = q.x * kp1.x + q.y * kp1.y + q.z * kp1.z + q.w * kp1.w;
        p0 += __shfl_xor_sync(0xffffffffu, p0, 1);
        p1 += __shfl_xor_sync(0xffffffffu, p1, 1);
        p0 += __shfl_xor_sync(0xffffffffu, p0, 2);
        p1 += __shfl_xor_sync(0xffffffffu, p1, 2);
        float e0 = expf(p0), e1 = expf(p1);
        z += e0 + e1;
        acc.x += e0 * vp0.x + e1 * vp1.x;
        acc.y += e0 * vp0.y + e1 * vp1.y;
        acc.z += e0 * vp0.z + e1 * vp1.z;
        acc.w += e0 * vp0.w + e1 * vp1.w;
    }
    if (e < dg) {
        int s = g_csr[off + e];
        const float4* kv = reinterpret_cast<const float4*>(kvbuf + (size_t)s * 256);
        float4 kp = kv[lane];
        float4 vp = kv[32 + lane];
        float p = q.x * kp.x + q.y * kp.y + q.z * kp.z + q.w * kp.w;
        p += __shfl_xor_sync(0xffffffffu, p, 1);
        p += __shfl_xor_sync(0xffffffffu, p, 2);
        float eh = expf(p);
        z += eh;
        acc.x += eh * vp.x; acc.y += eh * vp.y;
        acc.z += eh * vp.z; acc.w += eh * vp.w;
    }
    if (z > 0.f) {
        float inv = 1.f / z;
        res.x += acc.x * inv; res.y += acc.y * inv;
        res.z += acc.z * inv; res.w += acc.w * inv;
    }
}

__global__ void agg_type_b() {   // relation 0: a -> b
    int w = (blockIdx.x * blockDim.x + threadIdx.x) >> 5;
    if (w >= NN) return;
    int lane = threadIdx.x & 31;
    float4 q = *reinterpret_cast<const float4*>(g_qb + (size_t)w * 128 + lane * 4);
    float4 res = make_float4(0.f, 0.f, 0.f, 0.f);
    rel_accum(w, lane, 0, g_kv[0], q, res);
    *reinterpret_cast<float4*>(g_t[1] + (size_t)w * 128 + lane * 4) = res;
}

__global__ void agg_type_a() {   // relations 1 (b->a) + 2 (a->a), summed
    int w = (blockIdx.x * blockDim.x + threadIdx.x) >> 5;
    if (w >= NN) return;
    int lane = threadIdx.x & 31;
    float4 q = *reinterpret_cast<const float4*>(g_qa + (size_t)w * 128 + lane * 4);
    float4 res = make_float4(0.f, 0.f, 0.f, 0.f);
    rel_accum(w, lane, 1, g_kv[1], q, res);
    rel_accum(w, lane, 2, g_kv[2], q, res);
    *reinterpret_cast<float4*>(g_t[0] + (size_t)w * 128 + lane * 4) = res;
}

// ---------------------------------------------------------------------------
// Row LayerNorm (warp per row, 128 cols)
// ---------------------------------------------------------------------------
__global__ void layernorm(float* __restrict__ X, const float* __restrict__ gamma,
                          const float* __restrict__ beta) {
    int w = (blockIdx.x * blockDim.x + threadIdx.x) >> 5;
    if (w >= NN) return;
    int lane = threadIdx.x & 31;
    float4 v = *reinterpret_cast<const float4*>(X + (size_t)w * 128 + lane * 4);
    float s  = v.x + v.y + v.z + v.w;
    float s2 = v.x * v.x + v.y * v.y + v.z * v.z + v.w * v.w;
#pragma unroll
    for (int ofs = 16; ofs > 0; ofs >>= 1) {
        s  += __shfl_xor_sync(0xffffffffu, s, ofs);
        s2 += __shfl_xor_sync(0xffffffffu, s2, ofs);
    }
    float mu   = s * (1.f / 128.f);
    float var  = s2 * (1.f / 128.f) - mu * mu;
    float rstd = rsqrtf(var + 1e-5f);
    float4 g = *reinterpret_cast<const float4*>(gamma + lane * 4);
    float4 b = *reinterpret_cast<const float4*>(beta + lane * 4);
    float4 o;
    o.x = (v.x - mu) * rstd * g.x + b.x;
    o.y = (v.y - mu) * rstd * g.y + b.y;
    o.z = (v.z - mu) * rstd * g.z + b.z;
    o.w = (v.w - mu) * rstd * g.w + b.w;
    *reinterpret_cast<float4*>(X + (size_t)w * 128 + lane * 4) = o;
}

// ---------------------------------------------------------------------------
// Launch
// ---------------------------------------------------------------------------
extern "C" void kernel_launch(void* const* d_in, const int* in_sizes, int n_in,
                              void* d_out, int out_size) {
    const float* h_a   = (const float*)d_in[0];
    const float* h_b   = (const float*)d_in[1];
    const float* Wk    = (const float*)d_in[2];
    const float* bk    = (const float*)d_in[3];
    const float* Wq    = (const float*)d_in[4];
    const float* bq    = (const float*)d_in[5];
    const float* Wv    = (const float*)d_in[6];
    const float* bv    = (const float*)d_in[7];
    const float* Wa    = (const float*)d_in[8];
    const float* ba    = (const float*)d_in[9];
    const float* gamma = (const float*)d_in[10];
    const float* beta  = (const float*)d_in[11];
    const float* W1    = (const float*)d_in[12];
    const float* b1    = (const float*)d_in[13];
    const float* W2    = (const float*)d_in[14];
    const float* b2    = (const float*)d_in[15];
    const float* pri   = (const float*)d_in[16];
    const float* att   = (const float*)d_in[17];
    const float* msg   = (const float*)d_in[18];
    const void* src0 = d_in[19]; const void* dst0 = d_in[20];
    const void* src1 = d_in[21]; const void* dst1 = d_in[22];
    const void* src2 = d_in[23]; const void* dst2 = d_in[24];
    float* out = (float*)d_out;

    float *p_qa, *p_qb, *p_kv, *p_t, *p_x, *p_ff, *p_Wkv, *p_bkv;
    cudaGetSymbolAddress((void**)&p_qa,  g_qa);
    cudaGetSymbolAddress((void**)&p_qb,  g_qb);
    cudaGetSymbolAddress((void**)&p_kv,  g_kv);
    cudaGetSymbolAddress((void**)&p_t,   g_t);
    cudaGetSymbolAddress((void**)&p_x,   g_x);
    cudaGetSymbolAddress((void**)&p_ff,  g_ff);
    cudaGetSymbolAddress((void**)&p_Wkv, g_Wkv);
    cudaGetSymbolAddress((void**)&p_bkv, g_bkv);

    const int gy = (NN + 127) / 128;           // 782
    const int eb = (EE + 255) / 256;
    const int wb = (NN * 32) / 256;            // 12500 (exact)

    // 0. reset + edge dtype detection
    zero_deg<<<(NSCAN + 255) / 256, 256>>>();
    detect_i32<<<(EE / 2 + 255) / 256, 256>>>((const int*)dst0);

    // 1. fused relation weights
    prep_weights<<<(6 * CIN * COUT + 255) / 256, 256>>>(Wk, bk, Wv, bv, pri, att, msg);

    // 2. projections (q per type; fused kp|vp per relation)
    tgemm<false,false,false><<<dim3(1, gy), 256>>>(h_a, Wq,                 bq,       nullptr, p_qa, NN, 128, 128);
    tgemm<false,false,false><<<dim3(1, gy), 256>>>(h_b, Wq + 128 * 128,     bq + 128, nullptr, p_qb, NN, 128, 128);
    tgemm<false,false,false><<<dim3(2, gy), 256>>>(h_a, p_Wkv,              p_bkv,       nullptr, p_kv,                      NN, 256, 128);
    tgemm<false,false,false><<<dim3(2, gy), 256>>>(h_b, p_Wkv + 128 * 256,  p_bkv + 256, nullptr, p_kv + (size_t)NN * 256,   NN, 256, 128);
    tgemm<false,false,false><<<dim3(2, gy), 256>>>(h_a, p_Wkv + 2*128*256,  p_bkv + 512, nullptr, p_kv + 2*(size_t)NN * 256, NN, 256, 128);

    // 3. CSR build (degree -> scan -> scatter)
    count_deg<<<eb, 256>>>(dst0, 0);
    count_deg<<<eb, 256>>>(dst1, 1);
    count_deg<<<eb, 256>>>(dst2, 2);
    scan1<<<SCAN_NB, SCAN_BS>>>();
    scan2<<<1, 512>>>();
    scan3<<<SCAN_NB, SCAN_BS>>>();
    scatter_edges<<<eb, 256>>>(src0, dst0, 0);
    scatter_edges<<<eb, 256>>>(src1, dst1, 1);
    scatter_edges<<<eb, 256>>>(src2, dst2, 2);

    // 4. attention aggregation (warp per dst node, no atomics)
    agg_type_b<<<wb, 256>>>();
    agg_type_a<<<wb, 256>>>();

    // 5. per-type update: relu(t)@Wa + ba + h -> LN -> relu(@W1+b1)@W2 + b2
    for (int t = 0; t < 2; t++) {
        const float* hres = t ? h_b : h_a;
        tgemm<true,false,true><<<dim3(1, gy), 256>>>(p_t + (size_t)t * NN * 128, Wa + (size_t)t * 128 * 128,
                                                     ba + t * 128, hres,
                                                     p_x + (size_t)t * NN * 128, NN, 128, 128);
        layernorm<<<wb, 256>>>(p_x + (size_t)t * NN * 128, gamma + t * 128, beta + t * 128);
        tgemm<false,true,false><<<dim3(4, gy), 256>>>(p_x + (size_t)t * NN * 128, W1 + (size_t)t * 128 * 512,
                                                      b1 + t * 512, nullptr, p_ff, NN, 512, 128);
        tgemm<false,false,false><<<dim3(1, gy), 256>>>(p_ff, W2 + (size_t)t * 512 * 128,
                                                       b2 + t * 128, nullptr,
                                                       out + (size_t)t * NN * 128, NN, 128, 512);
    }
}